// round 5
// baseline (speedup 1.0000x reference)
#include <cuda_runtime.h>
#include <cuda_fp16.h>

// Problem constants (fixed shapes for this problem instance)
#define NN 100000   // nodes
#define NE 800000   // edges
#define VC 256      // vocab
#define DM 256      // node dim == hidden == vocab
#define NM 10000    // masked outputs

#define SB 512
#define NSB ((NN + SB - 1) / SB)   // 196 scan blocks

// ---------------- scratch (device globals; no allocation allowed) ----------
__device__ int   g_deg[NN];
__device__ int   g_cur[NN];
__device__ int   g_off[NN];
__device__ int   g_bsum[NSB];
__device__ float g_dinv[NN];
__device__ int   g_masked[NN];
__device__ int   g_needed[NN];
__device__ __align__(16) __half g_EWh[VC * DM];    // emb @ W1, fp16 (128 KB)
__device__ __align__(16) __half g_out1h[NN * DM];  // layer-1 pre-activation, fp16 (51 MB)
__device__ __align__(16) float  g_aggc[NM * DM];   // layer-2 aggregate, compact (10 MB)
__device__ __align__(16) int4   g_edge[NE];        // {x[src], src, coef_bits, 0} per CSR slot

// ---------------- kernels ---------------------------------------------------

__global__ void k_init(void) {
    int i = blockIdx.x * blockDim.x + threadIdx.x;
    if (i < NN) { g_deg[i] = 1; g_cur[i] = 0; g_masked[i] = 0; g_needed[i] = 0; }
}

__global__ void k_deg(const int* __restrict__ ei) {
    int e = blockIdx.x * blockDim.x + threadIdx.x;
    if (e < NE) atomicAdd(&g_deg[ei[NE + e]], 1);
}

// masked nodes are also "needed" (self term of layer-2 reads out1[node])
__global__ void k_mark(const int* __restrict__ mask) {
    int j = blockIdx.x * blockDim.x + threadIdx.x;
    if (j < NM) { int n = mask[j]; g_masked[n] = 1; g_needed[n] = 1; }
}

__global__ void k_dinv(void) {
    int i = blockIdx.x * blockDim.x + threadIdx.x;
    if (i < NN) g_dinv[i] = rsqrtf((float)g_deg[i]);
}

// ---- exclusive prefix scan of (deg-1) -> CSR row offsets -------------------
__global__ void k_scanA(void) {
    __shared__ int s[SB];
    int i = blockIdx.x * SB + threadIdx.x;
    int v = (i < NN) ? (g_deg[i] - 1) : 0;
    s[threadIdx.x] = v;
    __syncthreads();
    for (int o = 1; o < SB; o <<= 1) {
        int t = (threadIdx.x >= o) ? s[threadIdx.x - o] : 0;
        __syncthreads();
        s[threadIdx.x] += t;
        __syncthreads();
    }
    int inc = s[threadIdx.x];
    if (i < NN) g_off[i] = inc - v;                 // exclusive
    if (threadIdx.x == SB - 1) g_bsum[blockIdx.x] = inc;
}

__global__ void k_scanB(void) {   // one block of 256 >= NSB
    __shared__ int s[256];
    int t = threadIdx.x;
    int v = (t < NSB) ? g_bsum[t] : 0;
    s[t] = v;
    __syncthreads();
    for (int o = 1; o < 256; o <<= 1) {
        int u = (t >= o) ? s[t - o] : 0;
        __syncthreads();
        s[t] += u;
        __syncthreads();
    }
    if (t < NSB) g_bsum[t] = s[t] - v;              // exclusive
}

__global__ void k_scanC(void) {
    int i = blockIdx.x * SB + threadIdx.x;
    if (i < NN) g_off[i] += g_bsum[blockIdx.x];
}

// EW = emb @ W1 (fp16 output): one block per emb row, emb row staged in smem
__global__ void k_ew(const float* __restrict__ emb, const float* __restrict__ W1) {
    __shared__ float row[DM];
    int r = blockIdx.x, c = threadIdx.x;
    row[c] = emb[r * DM + c];
    __syncthreads();
    float acc = 0.f;
#pragma unroll 8
    for (int k = 0; k < DM; k++) acc += row[k] * W1[k * DM + c];
    g_EWh[r * DM + c] = __float2half(acc);
}

// place edges into CSR slots (single 16B record); flag srcs of masked dsts
__global__ void k_place(const int* __restrict__ ei, const int* __restrict__ x) {
    int e = blockIdx.x * blockDim.x + threadIdx.x;
    if (e >= NE) return;
    int s = ei[e];
    int d = ei[NE + e];
    float coef = g_dinv[s] * g_dinv[d];
    int slot = g_off[d] + atomicAdd(&g_cur[d], 1);
    g_edge[slot] = make_int4(x[s], s, __float_as_int(coef), 0);
    if (g_masked[d]) g_needed[s] = 1;
}

// layer-1 gather: out1[i] = b1 + dinv[i]^2*EW[x[i]] + sum coef*EW[x[src]]
// 64 threads per node, 4 features per thread (fp16 EW, fp32 accumulate)
__global__ void k_gather1(const int* __restrict__ x, const float* __restrict__ b1) {
    int node = blockIdx.x * 4 + (threadIdx.x >> 6);
    if (node >= NN) return;
    if (!g_needed[node]) return;                    // uniform per 64-thread group
    int q = threadIdx.x & 63;

    const uint2* EW2 = reinterpret_cast<const uint2*>(g_EWh);  // 4 halves / elem
    float di = g_dinv[node];
    float dd = di * di;

    uint2 w0u = EW2[x[node] * 64 + q];
    __half2 w0a = *reinterpret_cast<__half2*>(&w0u.x);
    __half2 w0b = *reinterpret_cast<__half2*>(&w0u.y);
    float4 bb = reinterpret_cast<const float4*>(b1)[q];
    float4 acc;
    acc.x = bb.x + dd * __half2float(__low2half(w0a));
    acc.y = bb.y + dd * __half2float(__high2half(w0a));
    acc.z = bb.z + dd * __half2float(__low2half(w0b));
    acc.w = bb.w + dd * __half2float(__high2half(w0b));

    int beg = g_off[node];
    int end = beg + g_deg[node] - 1;
    for (int k = beg; k < end; k++) {
        int4 rec = g_edge[k];                       // broadcast within group
        float c = __int_as_float(rec.z);
        uint2 wu = EW2[rec.x * 64 + q];
        __half2 wa = *reinterpret_cast<__half2*>(&wu.x);
        __half2 wb = *reinterpret_cast<__half2*>(&wu.y);
        acc.x += c * __half2float(__low2half(wa));
        acc.y += c * __half2float(__high2half(wa));
        acc.z += c * __half2float(__low2half(wb));
        acc.w += c * __half2float(__high2half(wb));
    }

    __half2 oa = __floats2half2_rn(acc.x, acc.y);
    __half2 ob = __floats2half2_rn(acc.z, acc.w);
    uint2 ou;
    ou.x = *reinterpret_cast<unsigned*>(&oa);
    ou.y = *reinterpret_cast<unsigned*>(&ob);
    reinterpret_cast<uint2*>(g_out1h)[node * 64 + q] = ou;
}

// layer-2 gather for masked entries only, compact output indexed by j:
//   aggc[j] = dinv^2*relu(out1[node]) + sum coef*relu(out1[src])
__global__ void k_gather2(const int* __restrict__ mask) {
    int gid = blockIdx.x * blockDim.x + threadIdx.x;
    int j = gid >> 6;
    if (j >= NM) return;
    int q = gid & 63;
    int node = mask[j];

    const uint2* O2 = reinterpret_cast<const uint2*>(g_out1h);
    float di = g_dinv[node];
    float dd = di * di;

    uint2 hu = O2[node * 64 + q];
    __half2 ha = *reinterpret_cast<__half2*>(&hu.x);
    __half2 hb = *reinterpret_cast<__half2*>(&hu.y);
    float4 acc;
    acc.x = dd * fmaxf(__half2float(__low2half(ha)), 0.f);
    acc.y = dd * fmaxf(__half2float(__high2half(ha)), 0.f);
    acc.z = dd * fmaxf(__half2float(__low2half(hb)), 0.f);
    acc.w = dd * fmaxf(__half2float(__high2half(hb)), 0.f);

    int beg = g_off[node];
    int end = beg + g_deg[node] - 1;
    for (int k = beg; k < end; k++) {
        int4 rec = g_edge[k];
        float c = __int_as_float(rec.z);
        uint2 su = O2[rec.y * 64 + q];
        __half2 sa = *reinterpret_cast<__half2*>(&su.x);
        __half2 sb = *reinterpret_cast<__half2*>(&su.y);
        acc.x += c * fmaxf(__half2float(__low2half(sa)), 0.f);
        acc.y += c * fmaxf(__half2float(__high2half(sa)), 0.f);
        acc.z += c * fmaxf(__half2float(__low2half(sb)), 0.f);
        acc.w += c * fmaxf(__half2float(__high2half(sb)), 0.f);
    }
    reinterpret_cast<float4*>(g_aggc)[j * 64 + q] = acc;
}

// final: out[j] = log_softmax(aggc[j] @ W2 + b2), 32 rows per block
// grid = ceil(NM/FROWS); the partial last tile is guarded (R4 bug: truncation
// left the last 16 rows unwritten -> rel_err exactly sqrt(16/10000) = 0.04)
#define FROWS 32
__global__ void __launch_bounds__(DM) k_final(const float* __restrict__ W2,
                                              const float* __restrict__ b2,
                                              float* __restrict__ out) {
    __shared__ float A[FROWS * DM];
    __shared__ float red[8];
    int c  = threadIdx.x;
    int j0 = blockIdx.x * FROWS;
    int nr = NM - j0; if (nr > FROWS) nr = FROWS;   // rows in this tile

#pragma unroll
    for (int r = 0; r < FROWS; r++)
        A[r * DM + c] = (r < nr) ? g_aggc[(j0 + r) * DM + c] : 0.f;
    __syncthreads();

    float bc = b2[c];
    float acc[FROWS];
#pragma unroll
    for (int r = 0; r < FROWS; r++) acc[r] = bc;

    const float4* A4 = reinterpret_cast<const float4*>(A);
#pragma unroll 2
    for (int kk = 0; kk < DM / 4; kk++) {
        float w0 = W2[(4 * kk + 0) * DM + c];
        float w1 = W2[(4 * kk + 1) * DM + c];
        float w2 = W2[(4 * kk + 2) * DM + c];
        float w3 = W2[(4 * kk + 3) * DM + c];
#pragma unroll
        for (int r = 0; r < FROWS; r++) {
            float4 a = A4[r * (DM / 4) + kk];
            acc[r] += a.x * w0 + a.y * w1 + a.z * w2 + a.w * w3;
        }
    }

    int lane = c & 31, wid = c >> 5;
#pragma unroll 1
    for (int r = 0; r < FROWS; r++) {
        if (r >= nr) break;                         // uniform across block
        float v = acc[r];
#pragma unroll
        for (int o = 16; o; o >>= 1) v = fmaxf(v, __shfl_xor_sync(0xffffffffu, v, o));
        if (lane == 0) red[wid] = v;
        __syncthreads();
        float m = red[0];
#pragma unroll
        for (int w = 1; w < 8; w++) m = fmaxf(m, red[w]);
        __syncthreads();
        float s = __expf(acc[r] - m);
#pragma unroll
        for (int o = 16; o; o >>= 1) s += __shfl_xor_sync(0xffffffffu, s, o);
        if (lane == 0) red[wid] = s;
        __syncthreads();
        float tot = red[0];
#pragma unroll
        for (int w = 1; w < 8; w++) tot += red[w];
        __syncthreads();
        out[(j0 + r) * DM + c] = acc[r] - m - logf(tot);
    }
}

// ---------------- launch -----------------------------------------------------
extern "C" void kernel_launch(void* const* d_in, const int* in_sizes, int n_in,
                              void* d_out, int out_size) {
    const int*   x    = (const int*)d_in[0];   // (100000,1) int32
    const int*   ei   = (const int*)d_in[1];   // (2,800000) int32: [src | dst]
    const int*   mask = (const int*)d_in[2];   // (10000,)   int32
    const float* emb  = (const float*)d_in[3]; // (256,256)
    const float* W1   = (const float*)d_in[4]; // (256,256)
    const float* b1   = (const float*)d_in[5]; // (256,)
    const float* W2   = (const float*)d_in[6]; // (256,256)
    const float* b2   = (const float*)d_in[7]; // (256,)
    float* out = (float*)d_out;                // (10000,256)

    (void)in_sizes; (void)n_in; (void)out_size;

    k_init <<<(NN + 255) / 256, 256>>>();
    k_deg  <<<(NE + 255) / 256, 256>>>(ei);
    k_mark <<<(NM + 255) / 256, 256>>>(mask);
    k_dinv <<<(NN + 255) / 256, 256>>>();
    k_scanA<<<NSB, SB>>>();
    k_scanB<<<1, 256>>>();
    k_scanC<<<NSB, SB>>>();
    k_ew   <<<VC, DM>>>(emb, W1);
    k_place<<<(NE + 255) / 256, 256>>>(ei, x);
    k_gather1<<<(NN + 3) / 4, 256>>>(x, b1);
    k_gather2<<<(NM * 64 + 255) / 256, 256>>>(mask);
    k_final<<<(NM + FROWS - 1) / FROWS, DM>>>(W2, b2, out);
}

// round 6
// speedup vs baseline: 1.0358x; 1.0358x over previous
#include <cuda_runtime.h>

// Problem constants (fixed shapes for this problem instance)
#define NN 100000   // nodes
#define NE 800000   // edges
#define VC 256      // vocab
#define DM 256      // node dim == hidden == vocab
#define NM 10000    // masked outputs

#define SB 512
#define NSB ((NN + SB - 1) / SB)   // 196 scan blocks

// ---------------- scratch (device globals; no allocation allowed) ----------
__device__ int   g_deg[NN];
__device__ int   g_cur[NN];
__device__ int   g_off[NN];
__device__ int   g_bsum[NSB];
__device__ float g_dinv[NN];
__device__ int   g_masked[NN];
__device__ int   g_needed[NN];
__device__ __align__(16) float g_EW[VC * DM];      // emb @ W1, fp32 (256 KB)
__device__ __align__(16) float g_out1[NN * DM];    // layer-1 pre-activation (102 MB)
__device__ __align__(16) float g_aggc[NM * DM];    // layer-2 aggregate, compact (10 MB)
__device__ __align__(16) int4  g_edge[NE];         // {x[src], src, coef_bits, 0} per CSR slot

// ---------------- kernels ---------------------------------------------------

__global__ void k_init(void) {
    int i = blockIdx.x * blockDim.x + threadIdx.x;
    if (i < NN) { g_deg[i] = 1; g_cur[i] = 0; g_masked[i] = 0; g_needed[i] = 0; }
}

// fused: degree count (first NE threads) + mask marking (next NM threads)
__global__ void k_degmark(const int* __restrict__ ei, const int* __restrict__ mask) {
    int t = blockIdx.x * blockDim.x + threadIdx.x;
    if (t < NE) {
        atomicAdd(&g_deg[ei[NE + t]], 1);
    } else if (t < NE + NM) {
        int n = mask[t - NE];
        g_masked[n] = 1;
        g_needed[n] = 1;          // self term of layer-2 reads out1[node]
    }
}

__global__ void k_dinv(void) {
    int i = blockIdx.x * blockDim.x + threadIdx.x;
    if (i < NN) g_dinv[i] = rsqrtf((float)g_deg[i]);
}

// ---- exclusive prefix scan of (deg-1) -> CSR row offsets -------------------
__global__ void k_scanA(void) {
    __shared__ int s[SB];
    int i = blockIdx.x * SB + threadIdx.x;
    int v = (i < NN) ? (g_deg[i] - 1) : 0;
    s[threadIdx.x] = v;
    __syncthreads();
    for (int o = 1; o < SB; o <<= 1) {
        int t = (threadIdx.x >= o) ? s[threadIdx.x - o] : 0;
        __syncthreads();
        s[threadIdx.x] += t;
        __syncthreads();
    }
    int inc = s[threadIdx.x];
    if (i < NN) g_off[i] = inc - v;                 // exclusive
    if (threadIdx.x == SB - 1) g_bsum[blockIdx.x] = inc;
}

__global__ void k_scanB(void) {   // one block of 256 >= NSB
    __shared__ int s[256];
    int t = threadIdx.x;
    int v = (t < NSB) ? g_bsum[t] : 0;
    s[t] = v;
    __syncthreads();
    for (int o = 1; o < 256; o <<= 1) {
        int u = (t >= o) ? s[t - o] : 0;
        __syncthreads();
        s[t] += u;
        __syncthreads();
    }
    if (t < NSB) g_bsum[t] = s[t] - v;              // exclusive
}

__global__ void k_scanC(void) {
    int i = blockIdx.x * SB + threadIdx.x;
    if (i < NN) g_off[i] += g_bsum[blockIdx.x];
}

// EW = emb @ W1 : one block per emb row, emb row staged in smem
__global__ void k_ew(const float* __restrict__ emb, const float* __restrict__ W1) {
    __shared__ float row[DM];
    int r = blockIdx.x, c = threadIdx.x;
    row[c] = emb[r * DM + c];
    __syncthreads();
    float acc = 0.f;
#pragma unroll 8
    for (int k = 0; k < DM; k++) acc += row[k] * W1[k * DM + c];
    g_EW[r * DM + c] = acc;
}

// place edges into CSR slots (single 16B record); flag srcs of masked dsts
__global__ void k_place(const int* __restrict__ ei, const int* __restrict__ x) {
    int e = blockIdx.x * blockDim.x + threadIdx.x;
    if (e >= NE) return;
    int s = ei[e];
    int d = ei[NE + e];
    float coef = g_dinv[s] * g_dinv[d];
    int slot = g_off[d] + atomicAdd(&g_cur[d], 1);
    g_edge[slot] = make_int4(x[s], s, __float_as_int(coef), 0);
    if (g_masked[d]) g_needed[s] = 1;
}

// layer-1 gather: out1[i] = b1 + dinv[i]^2*EW[x[i]] + sum coef*EW[x[src]]
// ONE WARP per node; lane handles 8 floats (two float4 chains).
// Edge records prefetched coalesced by lane, broadcast via shfl (no LDG in k-loop).
__global__ void k_gather1(const int* __restrict__ x, const float* __restrict__ b1) {
    int node = blockIdx.x * 8 + (threadIdx.x >> 5);
    if (node >= NN) return;
    if (!g_needed[node]) return;                    // warp-uniform
    int lane = threadIdx.x & 31;

    const float4* EW4 = reinterpret_cast<const float4*>(g_EW);
    float di = g_dinv[node];
    float dd = di * di;
    int   xn = x[node];

    float4 wa = EW4[xn * 64 + lane];
    float4 wb = EW4[xn * 64 + 32 + lane];
    float4 ba = reinterpret_cast<const float4*>(b1)[lane];
    float4 bbv = reinterpret_cast<const float4*>(b1)[32 + lane];
    float4 acc0 = make_float4(ba.x + dd * wa.x, ba.y + dd * wa.y,
                              ba.z + dd * wa.z, ba.w + dd * wa.w);
    float4 acc1 = make_float4(bbv.x + dd * wb.x, bbv.y + dd * wb.y,
                              bbv.z + dd * wb.z, bbv.w + dd * wb.w);

    int beg = g_off[node];
    int nedge = g_deg[node] - 1;
    for (int base = 0; base < nedge; base += 32) {
        int  rem = nedge - base;
        int  cnt = rem < 32 ? rem : 32;
        int4 rec = make_int4(0, 0, 0, 0);
        if (lane < cnt) rec = g_edge[beg + base + lane];   // coalesced
#pragma unroll 1
        for (int k = 0; k < cnt; k++) {
            float c  = __int_as_float(__shfl_sync(0xffffffffu, rec.z, k));
            int   xs = __shfl_sync(0xffffffffu, rec.x, k);
            float4 ea = EW4[xs * 64 + lane];
            float4 eb = EW4[xs * 64 + 32 + lane];
            acc0.x += c * ea.x; acc0.y += c * ea.y; acc0.z += c * ea.z; acc0.w += c * ea.w;
            acc1.x += c * eb.x; acc1.y += c * eb.y; acc1.z += c * eb.z; acc1.w += c * eb.w;
        }
    }
    reinterpret_cast<float4*>(g_out1)[node * 64 + lane]      = acc0;
    reinterpret_cast<float4*>(g_out1)[node * 64 + 32 + lane] = acc1;
}

// layer-2 gather for masked entries only (compact j-indexed output):
//   aggc[j] = dinv^2*relu(out1[node]) + sum coef*relu(out1[src])
__global__ void k_gather2(const int* __restrict__ mask) {
    int j = blockIdx.x * 8 + (threadIdx.x >> 5);
    if (j >= NM) return;
    int lane = threadIdx.x & 31;
    int node = mask[j];

    const float4* O4 = reinterpret_cast<const float4*>(g_out1);
    float di = g_dinv[node];
    float dd = di * di;

    float4 ha = O4[node * 64 + lane];
    float4 hb = O4[node * 64 + 32 + lane];
    float4 acc0 = make_float4(dd * fmaxf(ha.x, 0.f), dd * fmaxf(ha.y, 0.f),
                              dd * fmaxf(ha.z, 0.f), dd * fmaxf(ha.w, 0.f));
    float4 acc1 = make_float4(dd * fmaxf(hb.x, 0.f), dd * fmaxf(hb.y, 0.f),
                              dd * fmaxf(hb.z, 0.f), dd * fmaxf(hb.w, 0.f));

    int beg = g_off[node];
    int nedge = g_deg[node] - 1;
    for (int base = 0; base < nedge; base += 32) {
        int  rem = nedge - base;
        int  cnt = rem < 32 ? rem : 32;
        int4 rec = make_int4(0, 0, 0, 0);
        if (lane < cnt) rec = g_edge[beg + base + lane];
#pragma unroll 1
        for (int k = 0; k < cnt; k++) {
            float c = __int_as_float(__shfl_sync(0xffffffffu, rec.z, k));
            int   s = __shfl_sync(0xffffffffu, rec.y, k);
            float4 sa = O4[s * 64 + lane];
            float4 sb = O4[s * 64 + 32 + lane];
            acc0.x += c * fmaxf(sa.x, 0.f); acc0.y += c * fmaxf(sa.y, 0.f);
            acc0.z += c * fmaxf(sa.z, 0.f); acc0.w += c * fmaxf(sa.w, 0.f);
            acc1.x += c * fmaxf(sb.x, 0.f); acc1.y += c * fmaxf(sb.y, 0.f);
            acc1.z += c * fmaxf(sb.z, 0.f); acc1.w += c * fmaxf(sb.w, 0.f);
        }
    }
    reinterpret_cast<float4*>(g_aggc)[j * 64 + lane]      = acc0;
    reinterpret_cast<float4*>(g_aggc)[j * 64 + 32 + lane] = acc1;
}

// final: out[j] = log_softmax(aggc[j] @ W2 + b2), 32 rows per block (tail guarded)
#define FROWS 32
__global__ void __launch_bounds__(DM) k_final(const float* __restrict__ W2,
                                              const float* __restrict__ b2,
                                              float* __restrict__ out) {
    __shared__ float A[FROWS * DM];
    __shared__ float red[8];
    int c  = threadIdx.x;
    int j0 = blockIdx.x * FROWS;
    int nr = NM - j0; if (nr > FROWS) nr = FROWS;

#pragma unroll
    for (int r = 0; r < FROWS; r++)
        A[r * DM + c] = (r < nr) ? g_aggc[(j0 + r) * DM + c] : 0.f;
    __syncthreads();

    float bc = b2[c];
    float acc[FROWS];
#pragma unroll
    for (int r = 0; r < FROWS; r++) acc[r] = bc;

    const float4* A4 = reinterpret_cast<const float4*>(A);
#pragma unroll 2
    for (int kk = 0; kk < DM / 4; kk++) {
        float w0 = W2[(4 * kk + 0) * DM + c];
        float w1 = W2[(4 * kk + 1) * DM + c];
        float w2 = W2[(4 * kk + 2) * DM + c];
        float w3 = W2[(4 * kk + 3) * DM + c];
#pragma unroll
        for (int r = 0; r < FROWS; r++) {
            float4 a = A4[r * (DM / 4) + kk];
            acc[r] += a.x * w0 + a.y * w1 + a.z * w2 + a.w * w3;
        }
    }

    int lane = c & 31, wid = c >> 5;
#pragma unroll 1
    for (int r = 0; r < FROWS; r++) {
        if (r >= nr) break;                         // uniform across block
        float v = acc[r];
#pragma unroll
        for (int o = 16; o; o >>= 1) v = fmaxf(v, __shfl_xor_sync(0xffffffffu, v, o));
        if (lane == 0) red[wid] = v;
        __syncthreads();
        float m = red[0];
#pragma unroll
        for (int w = 1; w < 8; w++) m = fmaxf(m, red[w]);
        __syncthreads();
        float s = __expf(acc[r] - m);
#pragma unroll
        for (int o = 16; o; o >>= 1) s += __shfl_xor_sync(0xffffffffu, s, o);
        if (lane == 0) red[wid] = s;
        __syncthreads();
        float tot = red[0];
#pragma unroll
        for (int w = 1; w < 8; w++) tot += red[w];
        __syncthreads();
        out[(j0 + r) * DM + c] = acc[r] - m - logf(tot);
    }
}

// ---------------- launch -----------------------------------------------------
extern "C" void kernel_launch(void* const* d_in, const int* in_sizes, int n_in,
                              void* d_out, int out_size) {
    const int*   x    = (const int*)d_in[0];   // (100000,1) int32
    const int*   ei   = (const int*)d_in[1];   // (2,800000) int32: [src | dst]
    const int*   mask = (const int*)d_in[2];   // (10000,)   int32
    const float* emb  = (const float*)d_in[3]; // (256,256)
    const float* W1   = (const float*)d_in[4]; // (256,256)
    const float* b1   = (const float*)d_in[5]; // (256,)
    const float* W2   = (const float*)d_in[6]; // (256,256)
    const float* b2   = (const float*)d_in[7]; // (256,)
    float* out = (float*)d_out;                // (10000,256)

    (void)in_sizes; (void)n_in; (void)out_size;

    k_init   <<<(NN + 255) / 256, 256>>>();
    k_degmark<<<(NE + NM + 255) / 256, 256>>>(ei, mask);
    k_dinv   <<<(NN + 255) / 256, 256>>>();
    k_scanA  <<<NSB, SB>>>();
    k_scanB  <<<1, 256>>>();
    k_scanC  <<<NSB, SB>>>();
    k_ew     <<<VC, DM>>>(emb, W1);
    k_place  <<<(NE + 255) / 256, 256>>>(ei, x);
    k_gather1<<<(NN + 7) / 8, 256>>>(x, b1);
    k_gather2<<<(NM + 7) / 8, 256>>>(mask);
    k_final  <<<(NM + FROWS - 1) / FROWS, DM>>>(W2, b2, out);
}